// round 6
// baseline (speedup 1.0000x reference)
#include <cuda_runtime.h>
#include <cuda_bf16.h>
#include <cstdint>

// ---------------------------------------------------------------------------
// Problem constants
// ---------------------------------------------------------------------------
#define BATCH   128
#define T_STEPS 256
#define IN_F    1024
#define OUT_C   512
#define M_TOTAL (BATCH * T_STEPS)   // 32768
#define NKT     32                  // IN_F / 32 k-chunks

// SNN hyperparameters
#define V_TH      0.4f
#define LEAK      0.01f
#define REFR_LEAK 0.01f
#define REFRAC    2.0f

// ---------------------------------------------------------------------------
// Device scratch (static __device__: allocation-guard safe)
// ---------------------------------------------------------------------------
__device__ __align__(128) unsigned char g_Bth[(size_t)OUT_C * IN_F * 2]; // 1MB
__device__ __align__(128) unsigned char g_Btl[(size_t)OUT_C * IN_F * 2]; // 1MB
__device__ float g_I[(size_t)M_TOTAL * OUT_C];                           // 64MB

// ---------------------------------------------------------------------------
// Helpers (base sm_80/90 ISA only — nothing 'a'-gated)
// ---------------------------------------------------------------------------
__device__ __forceinline__ uint32_t smem_u32(const void* p) {
    uint32_t a;
    asm("{ .reg .u64 t; cvta.to.shared.u64 t, %1; cvt.u32.u64 %0, t; }"
        : "=r"(a) : "l"(p));
    return a;
}

__device__ __forceinline__ void cp_async16(uint32_t dst, const void* src) {
    asm volatile("cp.async.cg.shared.global [%0], [%1], 16;"
                 :: "r"(dst), "l"(src) : "memory");
}
#define CP_COMMIT() asm volatile("cp.async.commit_group;" ::: "memory")

__device__ __forceinline__ void ldmatrix_x4(uint32_t* r, uint32_t addr) {
    asm volatile("ldmatrix.sync.aligned.m8n8.x4.shared.b16 {%0,%1,%2,%3}, [%4];"
                 : "=r"(r[0]), "=r"(r[1]), "=r"(r[2]), "=r"(r[3]) : "r"(addr));
}

__device__ __forceinline__ void mma16816(float* d, const uint32_t* a,
                                         uint32_t b0, uint32_t b1) {
    asm volatile(
        "mma.sync.aligned.m16n8k16.row.col.f32.bf16.bf16.f32 "
        "{%0,%1,%2,%3}, {%4,%5,%6,%7}, {%8,%9}, {%0,%1,%2,%3};"
        : "+f"(d[0]), "+f"(d[1]), "+f"(d[2]), "+f"(d[3])
        : "r"(a[0]), "r"(a[1]), "r"(a[2]), "r"(a[3]), "r"(b0), "r"(b1));
}

// Swizzled byte offset within a 128-row x 64-byte tile (conflict-free ldmatrix).
// Packs 2 rows per 128B line: line = r>>1 -> +32 rows == +16 lines == +2048 B.
__device__ __forceinline__ uint32_t tile_off(int r, int c) {
    int line = r >> 1;
    int ch8 = (((r & 1) * 4 + c) ^ (line & 7));
    return (uint32_t)(line * 128 + ch8 * 16);
}

// ---------------------------------------------------------------------------
// conv_B: W fp32 [1024 k][512 n] -> Bt_hi / Bt_lo bf16 [n][1024 k]
// ---------------------------------------------------------------------------
__global__ __launch_bounds__(256)
void conv_B_kernel(const float* __restrict__ W) {
    const uint32_t i = blockIdx.x * 256 + threadIdx.x;   // 0 .. 524287
    const uint32_t k = i & 1023;
    const uint32_t n = i >> 10;
    float w = W[(size_t)k * OUT_C + n];
    __nv_bfloat16 hi = __float2bfloat16_rn(w);
    __nv_bfloat16 lo = __float2bfloat16_rn(w - __bfloat162float(hi));
    *(unsigned short*)(g_Bth + ((size_t)n * IN_F + k) * 2) = __bfloat16_as_ushort(hi);
    *(unsigned short*)(g_Btl + ((size_t)n * IN_F + k) * 2) = __bfloat16_as_ushort(lo);
}

// ---------------------------------------------------------------------------
// Fused GEMM: g_I[32768][512] = x[32768][1024] @ W, via bf16 3-term split:
//   hi_A*hi_B + hi_A*lo_B + lo_A*hi_B, fp32 accumulate (mma.sync 16x8x16).
// A converted in-register from fp32 x (no pre-pass). CTA 128x128, BK=32,
// 8 warps (4x2, warp tile 32x64). A: LDG->cvt->STS double-buffer.
// B: cp.async double-buffer of hi & lo tiles.
// ---------------------------------------------------------------------------
#define AH_OFF 0
#define AL_OFF 16384
#define BH_OFF 32768
#define BL_OFF 49152
#define GEMM_SMEM 65536

__global__ __launch_bounds__(256)
void snn_gemm_fused(const float* __restrict__ x) {
    extern __shared__ __align__(1024) unsigned char dsm[];
    const uint32_t sb = smem_u32(dsm);

    const int tid  = threadIdx.x;
    const int lane = tid & 31;
    const int wid  = tid >> 5;
    const int wm   = wid >> 1;          // 0..3
    const int wn   = wid & 1;           // 0..1
    const int mBase = blockIdx.y * 128;
    const int nBase = blockIdx.x * 128;

    // ---- A fp32 load mapping: 4 float4 per thread per k-chunk ----
    const int c4  = tid & 7;            // float4 column within 32-k chunk
    const int ra0 = tid >> 3;           // row 0..31 (+32*j)
    const float* gx = x + (size_t)(mBase + ra0) * IN_F + c4 * 4;

    // ---- B cp.async mapping: 2 chunks per thread per tile type ----
    const int rb0 = tid >> 2, cb0 = tid & 3;
    const int rb1 = (tid + 256) >> 2, cb1 = tid & 3;
    const uint32_t offB0 = tile_off(rb0, cb0), offB1 = tile_off(rb1, cb1);
    const unsigned char* gBh0 = g_Bth + (size_t)(nBase + rb0) * (IN_F * 2);
    const unsigned char* gBh1 = g_Bth + (size_t)(nBase + rb1) * (IN_F * 2);
    const unsigned char* gBl0 = g_Btl + (size_t)(nBase + rb0) * (IN_F * 2);
    const unsigned char* gBl1 = g_Btl + (size_t)(nBase + rb1) * (IN_F * 2);

    auto load_B = [&](int stg, int kt) {
        const uint32_t kb = (uint32_t)kt * 64;
        cp_async16(sb + BH_OFF + stg * 8192 + offB0, gBh0 + kb + cb0 * 16);
        cp_async16(sb + BH_OFF + stg * 8192 + offB1, gBh1 + kb + cb1 * 16);
        cp_async16(sb + BL_OFF + stg * 8192 + offB0, gBl0 + kb + cb0 * 16);
        cp_async16(sb + BL_OFF + stg * 8192 + offB1, gBl1 + kb + cb1 * 16);
    };

    float acc[2][8][4];
    #pragma unroll
    for (int mf = 0; mf < 2; mf++)
        #pragma unroll
        for (int nf = 0; nf < 8; nf++)
            #pragma unroll
            for (int d = 0; d < 4; d++) acc[mf][nf][d] = 0.0f;

    const int lrow = (lane & 7) + 8 * ((lane >> 3) & 1);
    const int lkc  = lane >> 4;
    const uint32_t offA_sts = tile_off(ra0, c4 >> 1) + (c4 & 1) * 8;

    // ---- prologue: prefetch A(0), issue B(0) ----
    float4 rA[4];
    #pragma unroll
    for (int j = 0; j < 4; j++)
        rA[j] = *(const float4*)(gx + (size_t)(j * 32) * IN_F);
    load_B(0, 0);
    CP_COMMIT();

    for (int kt = 0; kt < NKT; kt++) {
        const int s = kt & 1;

        // issue next B stage
        if (kt + 1 < NKT) { load_B(s ^ 1, kt + 1); }
        CP_COMMIT();

        // convert prefetched A regs -> STS into stage s (hi & lo tiles)
        #pragma unroll
        for (int j = 0; j < 4; j++) {
            float4 v = rA[j];
            __nv_bfloat16 h0 = __float2bfloat16_rn(v.x);
            __nv_bfloat16 h1 = __float2bfloat16_rn(v.y);
            __nv_bfloat16 h2 = __float2bfloat16_rn(v.z);
            __nv_bfloat16 h3 = __float2bfloat16_rn(v.w);
            __nv_bfloat16 l0 = __float2bfloat16_rn(v.x - __bfloat162float(h0));
            __nv_bfloat16 l1 = __float2bfloat16_rn(v.y - __bfloat162float(h1));
            __nv_bfloat16 l2 = __float2bfloat16_rn(v.z - __bfloat162float(h2));
            __nv_bfloat16 l3 = __float2bfloat16_rn(v.w - __bfloat162float(h3));
            uint2 ph, pl;
            ph.x = ((uint32_t)__bfloat16_as_ushort(h1) << 16) | __bfloat16_as_ushort(h0);
            ph.y = ((uint32_t)__bfloat16_as_ushort(h3) << 16) | __bfloat16_as_ushort(h2);
            pl.x = ((uint32_t)__bfloat16_as_ushort(l1) << 16) | __bfloat16_as_ushort(l0);
            pl.y = ((uint32_t)__bfloat16_as_ushort(l3) << 16) | __bfloat16_as_ushort(l2);
            // +32 rows == +16 lines == +2048 bytes in the packed-swizzled tile
            const uint32_t o = offA_sts + (uint32_t)j * 2048;
            *(uint2*)(dsm + AH_OFF + s * 8192 + o) = ph;
            *(uint2*)(dsm + AL_OFF + s * 8192 + o) = pl;
        }

        // prefetch A for next chunk
        if (kt + 1 < NKT) {
            const float* gxx = gx + (kt + 1) * 32;
            #pragma unroll
            for (int j = 0; j < 4; j++)
                rA[j] = *(const float4*)(gxx + (size_t)(j * 32) * IN_F);
        }

        // wait for B(kt); make A STS visible
        if (kt + 1 < NKT)
            asm volatile("cp.async.wait_group 1;" ::: "memory");
        else
            asm volatile("cp.async.wait_group 0;" ::: "memory");
        __syncthreads();

        // ---- MMA: 3 term-sets over this 32-k chunk ----
        const uint32_t bAh = sb + AH_OFF + s * 8192;
        const uint32_t bAl = sb + AL_OFF + s * 8192;
        const uint32_t bBh = sb + BH_OFF + s * 8192;
        const uint32_t bBl = sb + BL_OFF + s * 8192;
        #pragma unroll
        for (int ks = 0; ks < 2; ks++) {
            const int ch = ks * 2 + lkc;
            uint32_t ah[2][4], al[2][4], bh[4][4], bl[4][4];
            #pragma unroll
            for (int mf = 0; mf < 2; mf++) {
                int r = wm * 32 + mf * 16 + lrow;
                ldmatrix_x4(ah[mf], bAh + tile_off(r, ch));
                ldmatrix_x4(al[mf], bAl + tile_off(r, ch));
            }
            #pragma unroll
            for (int g = 0; g < 4; g++) {
                int r = wn * 64 + g * 16 + lrow;
                ldmatrix_x4(bh[g], bBh + tile_off(r, ch));
                ldmatrix_x4(bl[g], bBl + tile_off(r, ch));
            }
            #pragma unroll
            for (int mf = 0; mf < 2; mf++)
                #pragma unroll
                for (int g = 0; g < 4; g++) {
                    mma16816(acc[mf][2 * g],     ah[mf], bh[g][0], bh[g][2]);
                    mma16816(acc[mf][2 * g + 1], ah[mf], bh[g][1], bh[g][3]);
                    mma16816(acc[mf][2 * g],     ah[mf], bl[g][0], bl[g][2]);
                    mma16816(acc[mf][2 * g + 1], ah[mf], bl[g][1], bl[g][3]);
                    mma16816(acc[mf][2 * g],     al[mf], bh[g][0], bh[g][2]);
                    mma16816(acc[mf][2 * g + 1], al[mf], bh[g][1], bh[g][3]);
                }
        }
        __syncthreads();
    }

    // ---- epilogue ----
    #pragma unroll
    for (int mf = 0; mf < 2; mf++) {
        #pragma unroll
        for (int nf = 0; nf < 8; nf++) {
            const int row = mBase + wm * 32 + mf * 16 + (lane >> 2);
            const int col = nBase + wn * 64 + nf * 8 + (lane & 3) * 2;
            float* p0 = g_I + (size_t)row * OUT_C + col;
            float* p1 = p0 + 8 * OUT_C;
            *(float2*)p0 = make_float2(acc[mf][nf][0], acc[mf][nf][1]);
            *(float2*)p1 = make_float2(acc[mf][nf][2], acc[mf][nf][3]);
        }
    }
}

// ---------------------------------------------------------------------------
// Branchless per-neuron scan over T. 16-wide batched loads for MLP.
// Exact replication of reference step semantics (masks from OLD mode).
// ---------------------------------------------------------------------------
__global__ __launch_bounds__(256)
void snn_scan_kernel(float* __restrict__ out) {
    const int idx = blockIdx.x * 256 + threadIdx.x;   // 0..65535
    const float* Ip = g_I + ((size_t)(idx >> 9)) * T_STEPS * OUT_C + (idx & 511);

    float V = 0.0f, refr = 0.0f, sc = 0.0f;
    int mode = 0;

    for (int t0 = 0; t0 < T_STEPS; t0 += 16) {
        float buf[16];
        #pragma unroll
        for (int j = 0; j < 16; j++)
            buf[j] = Ip[(size_t)(t0 + j) * OUT_C];
        #pragma unroll
        for (int j = 0; j < 16; j++) {
            const float I = buf[j];
            const float v_std = fmaxf(V + I - LEAK, 0.0f);       // STD_POT=0
            const bool  fire  = (mode == 0) && (v_std > V_TH);   // strict >
            const float r_abs = fmaxf(refr - 1.0f, 0.0f);
            const bool  done  = (r_abs <= 0.0f);
            const float v_abs = fmaxf(V, 0.0f);                  // REFR_POT=0
            const float v_rel = fmaxf(V + REFR_LEAK, 0.0f);
            const bool  back  = (v_rel > 0.0f);                  // STD_POT=0

            const float Vn = (mode == 0) ? (fire ? 0.0f : v_std)
                           : (mode == 1) ? v_abs : v_rel;
            const float rn = (mode == 0) ? (fire ? REFRAC : refr)
                           : (mode == 1) ? r_abs : refr;
            const int   mn = (mode == 0) ? (fire ? 1 : 0)
                           : (mode == 1) ? (done ? 2 : 1)
                           : (back ? 0 : 2);
            sc += fire ? 1.0f : 0.0f;
            V = Vn; refr = rn; mode = mn;
        }
    }
    out[idx] = sc;
}

// ---------------------------------------------------------------------------
extern "C" void kernel_launch(void* const* d_in, const int* in_sizes, int n_in,
                              void* d_out, int out_size) {
    const float* x_seq = (const float*)d_in[0];  // [B, T, F]
    const float* W     = (const float*)d_in[1];  // [F, C]
    float* out = (float*)d_out;                  // [B, C]

    cudaFuncSetAttribute(snn_gemm_fused,
                         cudaFuncAttributeMaxDynamicSharedMemorySize, GEMM_SMEM);

    conv_B_kernel<<<(IN_F * OUT_C) / 256, 256>>>(W);

    dim3 gemmGrid(OUT_C / 128, M_TOTAL / 128);   // (4, 256)
    snn_gemm_fused<<<gemmGrid, 256, GEMM_SMEM>>>(x_seq);

    snn_scan_kernel<<<(BATCH * OUT_C) / 256, 256>>>(out);
}

// round 7
// speedup vs baseline: 1.1566x; 1.1566x over previous
#include <cuda_runtime.h>
#include <cuda_bf16.h>
#include <cstdint>

// ---------------------------------------------------------------------------
// Problem constants
// ---------------------------------------------------------------------------
#define BATCH   128
#define T_STEPS 256
#define IN_F    1024
#define OUT_C   512
#define M_TOTAL (BATCH * T_STEPS)   // 32768
#define NKT     32                  // IN_F / 32 k-chunks

// SNN hyperparameters
#define V_TH      0.4f
#define LEAK      0.01f
#define REFR_LEAK 0.01f
#define REFRAC    2.0f

// ---------------------------------------------------------------------------
// Device scratch (static __device__: allocation-guard safe)
// ---------------------------------------------------------------------------
__device__ __align__(128) unsigned char g_Ah[(size_t)M_TOTAL * IN_F * 2]; // 64MB
__device__ __align__(128) unsigned char g_Al[(size_t)M_TOTAL * IN_F * 2]; // 64MB
__device__ __align__(128) unsigned char g_Bh[(size_t)OUT_C * IN_F * 2];   // 1MB
__device__ __align__(128) unsigned char g_Bl[(size_t)OUT_C * IN_F * 2];   // 1MB
__device__ float g_I[(size_t)M_TOTAL * OUT_C];                            // 64MB

// ---------------------------------------------------------------------------
// Helpers (base sm_80/90 ISA only — nothing 'a'-gated)
// ---------------------------------------------------------------------------
__device__ __forceinline__ uint32_t smem_u32(const void* p) {
    uint32_t a;
    asm("{ .reg .u64 t; cvta.to.shared.u64 t, %1; cvt.u32.u64 %0, t; }"
        : "=r"(a) : "l"(p));
    return a;
}

__device__ __forceinline__ void cp_async16(uint32_t dst, const void* src) {
    asm volatile("cp.async.cg.shared.global [%0], [%1], 16;"
                 :: "r"(dst), "l"(src) : "memory");
}
#define CP_COMMIT() asm volatile("cp.async.commit_group;" ::: "memory")
#define CP_WAIT1()  asm volatile("cp.async.wait_group 1;" ::: "memory")

__device__ __forceinline__ void ldmatrix_x4(uint32_t* r, uint32_t addr) {
    asm volatile("ldmatrix.sync.aligned.m8n8.x4.shared.b16 {%0,%1,%2,%3}, [%4];"
                 : "=r"(r[0]), "=r"(r[1]), "=r"(r[2]), "=r"(r[3]) : "r"(addr));
}

__device__ __forceinline__ void mma16816(float* d, const uint32_t* a,
                                         uint32_t b0, uint32_t b1) {
    asm volatile(
        "mma.sync.aligned.m16n8k16.row.col.f32.bf16.bf16.f32 "
        "{%0,%1,%2,%3}, {%4,%5,%6,%7}, {%8,%9}, {%0,%1,%2,%3};"
        : "+f"(d[0]), "+f"(d[1]), "+f"(d[2]), "+f"(d[3])
        : "r"(a[0]), "r"(a[1]), "r"(a[2]), "r"(a[3]), "r"(b0), "r"(b1));
}

// Swizzled byte offset within a 128-row x 64-byte tile (conflict-free ldmatrix).
// Packs 2 rows per 128B line: line = r>>1 -> +32 rows == +2048 B.
__device__ __forceinline__ uint32_t tile_off(int r, int c) {
    int line = r >> 1;
    int ch8 = (((r & 1) * 4 + c) ^ (line & 7));
    return (uint32_t)(line * 128 + ch8 * 16);
}

// ---------------------------------------------------------------------------
// conv_A: x fp32 [32768][1024] -> g_Ah / g_Al bf16 [m][1024] (flat row-major)
// ---------------------------------------------------------------------------
__global__ __launch_bounds__(256)
void conv_A_kernel(const float4* __restrict__ x) {
    const uint32_t i = blockIdx.x * 256 + threadIdx.x;   // 0 .. 8388607
    const uint32_t m  = i >> 8;
    const uint32_t ko = (i & 255) * 4;
    float4 v = x[i];

    __nv_bfloat16 h0 = __float2bfloat16_rn(v.x);
    __nv_bfloat16 h1 = __float2bfloat16_rn(v.y);
    __nv_bfloat16 h2 = __float2bfloat16_rn(v.z);
    __nv_bfloat16 h3 = __float2bfloat16_rn(v.w);
    __nv_bfloat16 l0 = __float2bfloat16_rn(v.x - __bfloat162float(h0));
    __nv_bfloat16 l1 = __float2bfloat16_rn(v.y - __bfloat162float(h1));
    __nv_bfloat16 l2 = __float2bfloat16_rn(v.z - __bfloat162float(h2));
    __nv_bfloat16 l3 = __float2bfloat16_rn(v.w - __bfloat162float(h3));

    uint2 ph, pl;
    ph.x = ((uint32_t)__bfloat16_as_ushort(h1) << 16) | __bfloat16_as_ushort(h0);
    ph.y = ((uint32_t)__bfloat16_as_ushort(h3) << 16) | __bfloat16_as_ushort(h2);
    pl.x = ((uint32_t)__bfloat16_as_ushort(l1) << 16) | __bfloat16_as_ushort(l0);
    pl.y = ((uint32_t)__bfloat16_as_ushort(l3) << 16) | __bfloat16_as_ushort(l2);

    *(uint2*)(g_Ah + ((size_t)m * IN_F + ko) * 2) = ph;
    *(uint2*)(g_Al + ((size_t)m * IN_F + ko) * 2) = pl;
}

// ---------------------------------------------------------------------------
// conv_B: W fp32 [1024 k][512 n] -> g_Bh / g_Bl bf16 [n][1024 k]
// ---------------------------------------------------------------------------
__global__ __launch_bounds__(256)
void conv_B_kernel(const float* __restrict__ W) {
    const uint32_t i = blockIdx.x * 256 + threadIdx.x;   // 0 .. 524287
    const uint32_t k = i & 1023;
    const uint32_t n = i >> 10;
    float w = W[(size_t)k * OUT_C + n];
    __nv_bfloat16 hi = __float2bfloat16_rn(w);
    __nv_bfloat16 lo = __float2bfloat16_rn(w - __bfloat162float(hi));
    *(unsigned short*)(g_Bh + ((size_t)n * IN_F + k) * 2) = __bfloat16_as_ushort(hi);
    *(unsigned short*)(g_Bl + ((size_t)n * IN_F + k) * 2) = __bfloat16_as_ushort(lo);
}

// ---------------------------------------------------------------------------
// GEMM: g_I = 3-term bf16 split (ah*bh + ah*bl + al*bh), fp32 accumulate.
// CTA 128x128, BK=32, 8 warps (4x2, warp tile 32x64), mma.sync 16x8x16.
// 3-stage cp.async pipeline; each stage holds Ah|Al|Bh|Bl 8KB tiles (32KB).
// ---------------------------------------------------------------------------
#define STG_SZ  32768
#define GEMM_SMEM (3 * STG_SZ)   // 96KB -> 2 CTAs/SM

__global__ __launch_bounds__(256, 2)
void snn_gemm_mma() {
    extern __shared__ __align__(1024) unsigned char dsm[];
    const uint32_t sb = smem_u32(dsm);

    const int tid  = threadIdx.x;
    const int lane = tid & 31;
    const int wid  = tid >> 5;
    const int wm   = wid >> 1;          // 0..3
    const int wn   = wid & 1;           // 0..1
    const int mBase = blockIdx.y * 128;
    const int nBase = blockIdx.x * 128;

    // cp.async mapping: 512 16B-chunks per 8KB tile -> 2 chunks/thread/tile
    const int r0 = tid >> 2, c0 = tid & 3;
    const int r1 = r0 + 64;
    const uint32_t offT0 = tile_off(r0, c0), offT1 = tile_off(r1, c0);

    const unsigned char* gAh0 = g_Ah + (size_t)(mBase + r0) * (IN_F * 2);
    const unsigned char* gAh1 = g_Ah + (size_t)(mBase + r1) * (IN_F * 2);
    const unsigned char* gAl0 = g_Al + (size_t)(mBase + r0) * (IN_F * 2);
    const unsigned char* gAl1 = g_Al + (size_t)(mBase + r1) * (IN_F * 2);
    const unsigned char* gBh0 = g_Bh + (size_t)(nBase + r0) * (IN_F * 2);
    const unsigned char* gBh1 = g_Bh + (size_t)(nBase + r1) * (IN_F * 2);
    const unsigned char* gBl0 = g_Bl + (size_t)(nBase + r0) * (IN_F * 2);
    const unsigned char* gBl1 = g_Bl + (size_t)(nBase + r1) * (IN_F * 2);

    auto load_stage = [&](int stg, int kt) {
        const uint32_t kb = (uint32_t)kt * 64 + c0 * 16;
        const uint32_t bs = sb + stg * STG_SZ;
        cp_async16(bs + offT0,          gAh0 + kb);
        cp_async16(bs + offT1,          gAh1 + kb);
        cp_async16(bs + 8192 + offT0,   gAl0 + kb);
        cp_async16(bs + 8192 + offT1,   gAl1 + kb);
        cp_async16(bs + 16384 + offT0,  gBh0 + kb);
        cp_async16(bs + 16384 + offT1,  gBh1 + kb);
        cp_async16(bs + 24576 + offT0,  gBl0 + kb);
        cp_async16(bs + 24576 + offT1,  gBl1 + kb);
    };

    float acc[2][8][4];
    #pragma unroll
    for (int mf = 0; mf < 2; mf++)
        #pragma unroll
        for (int nf = 0; nf < 8; nf++)
            #pragma unroll
            for (int d = 0; d < 4; d++) acc[mf][nf][d] = 0.0f;

    const int lrow = (lane & 7) + 8 * ((lane >> 3) & 1);
    const int lkc  = lane >> 4;

    load_stage(0, 0); CP_COMMIT();
    load_stage(1, 1); CP_COMMIT();

    for (int kt = 0; kt < NKT; kt++) {
        CP_WAIT1();
        __syncthreads();
        if (kt + 2 < NKT) load_stage((kt + 2) % 3, kt + 2);
        CP_COMMIT();

        const uint32_t bs = sb + (kt % 3) * STG_SZ;
        #pragma unroll
        for (int ks = 0; ks < 2; ks++) {
            const int ch = ks * 2 + lkc;
            uint32_t ah[2][4], al[2][4];
            #pragma unroll
            for (int mf = 0; mf < 2; mf++) {
                const uint32_t ao = tile_off(wm * 32 + mf * 16 + lrow, ch);
                ldmatrix_x4(ah[mf], bs + ao);
                ldmatrix_x4(al[mf], bs + 8192 + ao);
            }
            #pragma unroll
            for (int g = 0; g < 4; g++) {
                const uint32_t bo = tile_off(wn * 64 + g * 16 + lrow, ch);
                uint32_t bh[4], bl[4];
                ldmatrix_x4(bh, bs + 16384 + bo);
                ldmatrix_x4(bl, bs + 24576 + bo);
                #pragma unroll
                for (int mf = 0; mf < 2; mf++) {
                    mma16816(acc[mf][2 * g],     ah[mf], bh[0], bh[2]);
                    mma16816(acc[mf][2 * g + 1], ah[mf], bh[1], bh[3]);
                    mma16816(acc[mf][2 * g],     ah[mf], bl[0], bl[2]);
                    mma16816(acc[mf][2 * g + 1], ah[mf], bl[1], bl[3]);
                    mma16816(acc[mf][2 * g],     al[mf], bh[0], bh[2]);
                    mma16816(acc[mf][2 * g + 1], al[mf], bh[1], bh[3]);
                }
            }
        }
        __syncthreads();
    }

    // ---- epilogue ----
    #pragma unroll
    for (int mf = 0; mf < 2; mf++) {
        #pragma unroll
        for (int nf = 0; nf < 8; nf++) {
            const int row = mBase + wm * 32 + mf * 16 + (lane >> 2);
            const int col = nBase + wn * 64 + nf * 8 + (lane & 3) * 2;
            float* p0 = g_I + (size_t)row * OUT_C + col;
            float* p1 = p0 + 8 * OUT_C;
            *(float2*)p0 = make_float2(acc[mf][nf][0], acc[mf][nf][1]);
            *(float2*)p1 = make_float2(acc[mf][nf][2], acc[mf][nf][3]);
        }
    }
}

// ---------------------------------------------------------------------------
// Branchless per-neuron scan over T. 16-wide batched loads for MLP.
// Exact replication of reference step semantics (masks from OLD mode).
// ---------------------------------------------------------------------------
__global__ __launch_bounds__(256)
void snn_scan_kernel(float* __restrict__ out) {
    const int idx = blockIdx.x * 256 + threadIdx.x;   // 0..65535
    const float* Ip = g_I + ((size_t)(idx >> 9)) * T_STEPS * OUT_C + (idx & 511);

    float V = 0.0f, refr = 0.0f, sc = 0.0f;
    int mode = 0;

    for (int t0 = 0; t0 < T_STEPS; t0 += 16) {
        float buf[16];
        #pragma unroll
        for (int j = 0; j < 16; j++)
            buf[j] = Ip[(size_t)(t0 + j) * OUT_C];
        #pragma unroll
        for (int j = 0; j < 16; j++) {
            const float I = buf[j];
            const float v_std = fmaxf(V + I - LEAK, 0.0f);       // STD_POT=0
            const bool  fire  = (mode == 0) && (v_std > V_TH);   // strict >
            const float r_abs = fmaxf(refr - 1.0f, 0.0f);
            const bool  done  = (r_abs <= 0.0f);
            const float v_abs = fmaxf(V, 0.0f);                  // REFR_POT=0
            const float v_rel = fmaxf(V + REFR_LEAK, 0.0f);
            const bool  back  = (v_rel > 0.0f);                  // STD_POT=0

            const float Vn = (mode == 0) ? (fire ? 0.0f : v_std)
                           : (mode == 1) ? v_abs : v_rel;
            const float rn = (mode == 0) ? (fire ? REFRAC : refr)
                           : (mode == 1) ? r_abs : refr;
            const int   mn = (mode == 0) ? (fire ? 1 : 0)
                           : (mode == 1) ? (done ? 2 : 1)
                           : (back ? 0 : 2);
            sc += fire ? 1.0f : 0.0f;
            V = Vn; refr = rn; mode = mn;
        }
    }
    out[idx] = sc;
}

// ---------------------------------------------------------------------------
extern "C" void kernel_launch(void* const* d_in, const int* in_sizes, int n_in,
                              void* d_out, int out_size) {
    const float* x_seq = (const float*)d_in[0];  // [B, T, F]
    const float* W     = (const float*)d_in[1];  // [F, C]
    float* out = (float*)d_out;                  // [B, C]

    cudaFuncSetAttribute(snn_gemm_mma,
                         cudaFuncAttributeMaxDynamicSharedMemorySize, GEMM_SMEM);

    conv_A_kernel<<<(M_TOTAL * IN_F / 4) / 256, 256>>>((const float4*)x_seq);
    conv_B_kernel<<<(IN_F * OUT_C) / 256, 256>>>(W);

    dim3 gemmGrid(OUT_C / 128, M_TOTAL / 128);   // (4, 256)
    snn_gemm_mma<<<gemmGrid, 256, GEMM_SMEM>>>();

    snn_scan_kernel<<<(BATCH * OUT_C) / 256, 256>>>(out);
}